// round 16
// baseline (speedup 1.0000x reference)
#include <cuda_runtime.h>
#include <cuda_fp16.h>
#include <math.h>

#define BSZ   2
#define CDIM  256
#define LDIM  4096
#define HEADS 8
#define HD    32
#define N3C   768

// fp16 scratch
__device__ __half g_xh [BSZ*LDIM*CDIM];   // x^T  [b][L][C]
__device__ __half g_w1t[N3C*CDIM];        // w1^T [768][256]
__device__ __half g_w2t[CDIM*CDIM];       // w2^T [256][256]
__device__ __half g_q[BSZ*HEADS*LDIM*HD]; // [bh][L][32]
__device__ __half g_k[BSZ*HEADS*LDIM*HD]; // [bh][L][32]
__device__ __half g_v[BSZ*HEADS*LDIM*HD]; // [bh][c][L] channel-major
__device__ __half g_o[BSZ*LDIM*CDIM];     // [b][L][C]

// fp16 m16n8k16
__device__ __forceinline__ void mma16(float* c, const unsigned* a, const unsigned* b) {
    asm volatile(
        "mma.sync.aligned.m16n8k16.row.col.f32.f16.f16.f32 "
        "{%0,%1,%2,%3},{%4,%5,%6,%7},{%8,%9},{%0,%1,%2,%3};"
        : "+f"(c[0]), "+f"(c[1]), "+f"(c[2]), "+f"(c[3])
        : "r"(a[0]), "r"(a[1]), "r"(a[2]), "r"(a[3]), "r"(b[0]), "r"(b[1]));
}

__device__ __forceinline__ unsigned pk2(float lo, float hi) {
    unsigned r;
    asm("cvt.rn.f16x2.f32 %0, %1, %2;" : "=r"(r) : "f"(hi), "f"(lo));
    return r;
}
__device__ __forceinline__ unsigned ex2h2(unsigned s) {
    unsigned r;
    asm("ex2.approx.f16x2 %0, %1;" : "=r"(r) : "r"(s));
    return r;
}

__device__ __forceinline__ void cp16(void* s, const void* g) {
    unsigned sa = (unsigned)__cvta_generic_to_shared(s);
    asm volatile("cp.async.cg.shared.global [%0], [%1], 16;" :: "r"(sa), "l"(g));
}
__device__ __forceinline__ void cp_commit() { asm volatile("cp.async.commit_group;"); }
__device__ __forceinline__ void cp_wait0()  { asm volatile("cp.async.wait_group 0;"); }

// ---------------------------------------------------------------------------
// Transpose + f32->f16 convert: dst[c][r] = (half)src[r][c]
// ---------------------------------------------------------------------------
__global__ void transpose_f2h(const float* __restrict__ src, __half* __restrict__ dst,
                              int rows, int cols) {
    __shared__ float tile[32][33];
    const int bz = blockIdx.z;
    src += (size_t)bz * rows * cols;
    dst += (size_t)bz * rows * cols;
    const int c0 = blockIdx.x * 32, r0 = blockIdx.y * 32;
    const int tx = threadIdx.x, ty = threadIdx.y;
    #pragma unroll
    for (int i = 0; i < 4; i++)
        tile[ty + 8 * i][tx] = src[(size_t)(r0 + ty + 8 * i) * cols + c0 + tx];
    __syncthreads();
    #pragma unroll
    for (int i = 0; i < 4; i++)
        dst[(size_t)(c0 + ty + 8 * i) * rows + r0 + tx] = __float2half_rn(tile[tx][ty + 8 * i]);
}

// ---------------------------------------------------------------------------
// Kernel 1: qkv via fp16 mma; 2-stage cp.async (EXACT R14 config).
// ---------------------------------------------------------------------------
__global__ void __launch_bounds__(256) qkv_gemm(const float* __restrict__ b1) {
    __shared__ __half Wt[2][64][40];
    __shared__ __half Xt[2][64][40];

    const int b  = blockIdx.z;
    const int m0 = blockIdx.x * 64;
    const int n0 = blockIdx.y * 64;
    const int t  = threadIdx.x;
    const int lane = t & 31;
    const int warp = t >> 5;
    const int wr = warp >> 1;
    const int wc = warp & 1;
    const int g  = lane >> 2;
    const int tg = lane & 3;

    const __half* xb = g_xh + (size_t)b * LDIM * CDIM;
    float acc[4][4] = {};

    const int s_row = t >> 2, s_seg = (t & 3) * 8;

    cp16(&Wt[0][s_row][s_seg], &g_w1t[(size_t)(n0 + s_row) * CDIM + s_seg]);
    cp16(&Xt[0][s_row][s_seg], &xb[(size_t)(m0 + s_row) * CDIM + s_seg]);
    cp_commit();

    #pragma unroll
    for (int i = 0; i < 8; i++) {
        const int cur = i & 1;
        cp_wait0();
        __syncthreads();
        if (i < 7) {
            const int nxt = 1 - cur;
            const int kn = (i + 1) * 32;
            cp16(&Wt[nxt][s_row][s_seg], &g_w1t[(size_t)(n0 + s_row) * CDIM + kn + s_seg]);
            cp16(&Xt[nxt][s_row][s_seg], &xb[(size_t)(m0 + s_row) * CDIM + kn + s_seg]);
            cp_commit();
        }
        #pragma unroll
        for (int ks = 0; ks < 2; ks++) {
            unsigned af[4];
            af[0] = *(const unsigned*)&Wt[cur][wr * 16 + g][16 * ks + 2 * tg];
            af[1] = *(const unsigned*)&Wt[cur][wr * 16 + g + 8][16 * ks + 2 * tg];
            af[2] = *(const unsigned*)&Wt[cur][wr * 16 + g][16 * ks + 2 * tg + 8];
            af[3] = *(const unsigned*)&Wt[cur][wr * 16 + g + 8][16 * ks + 2 * tg + 8];
            #pragma unroll
            for (int mb = 0; mb < 4; mb++) {
                int mc = wc * 32 + mb * 8 + g;
                unsigned bf[2] = {*(const unsigned*)&Xt[cur][mc][16 * ks + 2 * tg],
                                  *(const unsigned*)&Xt[cur][mc][16 * ks + 2 * tg + 8]};
                mma16(acc[mb], af, bf);
            }
        }
    }

    const float q_scale = 0.1767766952966368811f * 1.4426950408889634f;
    const int n_r0 = n0 + wr * 16 + g;
    const int n_r1 = n_r0 + 8;
    const int k3_0 = n_r0 % 3, h_0 = (n_r0 / 3) & 7, c_0 = n_r0 / 24;
    const int k3_1 = n_r1 % 3, h_1 = (n_r1 / 3) & 7, c_1 = n_r1 / 24;
    const float bias0 = b1[n_r0], bias1 = b1[n_r1];
    const float sc0 = (k3_0 == 0) ? q_scale : 1.f;
    const float sc1 = (k3_1 == 0) ? q_scale : 1.f;
    const int bh0 = b * HEADS + h_0, bh1 = b * HEADS + h_1;

    #pragma unroll
    for (int mb = 0; mb < 4; mb++) {
        int mA = m0 + wc * 32 + mb * 8 + 2 * tg;
        float v00 = (acc[mb][0] + bias0) * sc0, v01 = (acc[mb][1] + bias0) * sc0;
        float v10 = (acc[mb][2] + bias1) * sc1, v11 = (acc[mb][3] + bias1) * sc1;
        if (k3_0 == 2) {
            *(__half2*)&g_v[((size_t)bh0 * HD + c_0) * LDIM + mA] = __floats2half2_rn(v00, v01);
        } else {
            __half* d = (k3_0 == 0) ? g_q : g_k;
            d[((size_t)bh0 * LDIM + mA)     * HD + c_0] = __float2half_rn(v00);
            d[((size_t)bh0 * LDIM + mA + 1) * HD + c_0] = __float2half_rn(v01);
        }
        if (k3_1 == 2) {
            *(__half2*)&g_v[((size_t)bh1 * HD + c_1) * LDIM + mA] = __floats2half2_rn(v10, v11);
        } else {
            __half* d = (k3_1 == 0) ? g_q : g_k;
            d[((size_t)bh1 * LDIM + mA)     * HD + c_1] = __float2half_rn(v10);
            d[((size_t)bh1 * LDIM + mA + 1) * HD + c_1] = __float2half_rn(v11);
        }
    }
}

// ---------------------------------------------------------------------------
// Kernel 2: banded attention, 128 queries per block (512 threads, 16 warps).
// K/V L2 + staging traffic per query ~halved vs 64q blocks. Per-warp work
// identical to R14. Exact full-tile-validity predicate for masking.
// ---------------------------------------------------------------------------
__global__ void __launch_bounds__(512) attn_kernel() {
    __shared__ __half Qs[128][40];
    __shared__ __half Ks[2][64][40];
    __shared__ __half Vt[2][32][72];
    __shared__ __half GsK[8][40];
    __shared__ __half Vgt[32][12];
    __shared__ float  Red[128][33];
    __shared__ float  Lsm[128][2];

    const int qt = blockIdx.x;
    const int bh = blockIdx.y;
    const int i0 = qt * 128;
    const int t  = threadIdx.x;
    const int lane = t & 31;
    const int warp = t >> 5;
    const int wr = warp >> 1;        // 0..7 row-block (16 rows)
    const int wc = warp & 1;         // key half
    const int g  = lane >> 2;
    const int tg = lane & 3;

    const __half* qb  = g_q + (size_t)bh * LDIM * HD;
    const __half* kb  = g_k + (size_t)bh * LDIM * HD;
    const __half* vbt = g_v + (size_t)bh * HD * LDIM;

    const bool hasG = (qt == 0) || (qt == 31);
    const int  tlo  = max(0, i0 - 512) >> 6;
    const int  thi  = min(LDIM - 1, i0 + 127 + 512) >> 6;
    const int  cnt  = hasG ? 64 : (thi - tlo + 1);
    const int  t0   = hasG ? 0 : tlo;

    // stage Q: 512 threads x 1 cp16 covers 128 rows x 32 halves
    const int q_row = t >> 2, q_seg = (t & 3) * 8;
    cp16(&Qs[q_row][q_seg], &qb[(size_t)(i0 + q_row) * HD + q_seg]);

    if (!hasG) {
        if (t < 16) {
            int row = t >> 2, seg = t & 3;
            int jr = (row == 0) ? 0 : (row == 1) ? 63 : (row == 2) ? 4032 : 4095;
            *(uint4*)&GsK[row][seg * 8] = *(const uint4*)&kb[(size_t)jr * HD + seg * 8];
        } else if (t < 32) {
            int row = 4 + ((t - 16) >> 2), seg = t & 3;
            uint4 z = {0u, 0u, 0u, 0u};
            *(uint4*)&GsK[row][seg * 8] = z;
        } else if (t < 64) {
            int c = t - 32;
            Vgt[c][0] = vbt[(size_t)c * LDIM + 0];
            Vgt[c][1] = vbt[(size_t)c * LDIM + 63];
            Vgt[c][2] = vbt[(size_t)c * LDIM + 4032];
            Vgt[c][3] = vbt[(size_t)c * LDIM + 4095];
            #pragma unroll
            for (int jj = 4; jj < 12; jj++) Vgt[c][jj] = __float2half(0.f);
        }
    }

    // K/V staging split: threads 0..255 -> Ks (64x32), 256..511 -> Vt (32x64)
    const bool doK = (t < 256);
    const int k_row = (t & 255) >> 2, k_seg = ((t & 255) & 3) * 8;
    const int v_row = (t & 255) >> 3, v_seg = ((t & 255) & 7) * 8;

    {   // prologue: first K/V tile -> buf 0
        const int j0 = t0 * 64;
        if (doK) cp16(&Ks[0][k_row][k_seg], &kb[(size_t)(j0 + k_row) * HD + k_seg]);
        else     cp16(&Vt[0][v_row][v_seg], &vbt[(size_t)v_row * LDIM + j0 + v_seg]);
        cp_commit();
    }
    cp_wait0();
    __syncthreads();

    unsigned aq[2][4];
    const int r0 = wr * 16 + g;
    const int r1 = r0 + 8;
    #pragma unroll
    for (int ks = 0; ks < 2; ks++) {
        aq[ks][0] = *(const unsigned*)&Qs[r0][16 * ks + 2 * tg];
        aq[ks][1] = *(const unsigned*)&Qs[r1][16 * ks + 2 * tg];
        aq[ks][2] = *(const unsigned*)&Qs[r0][16 * ks + 2 * tg + 8];
        aq[ks][3] = *(const unsigned*)&Qs[r1][16 * ks + 2 * tg + 8];
    }

    const int ir0 = i0 + r0, ir1 = i0 + r1;
    const bool ig0 = (ir0 == 0) || (ir0 == 63) || (ir0 == 4032) || (ir0 == 4095);
    const bool ig1 = (ir1 == 0) || (ir1 == 63) || (ir1 == 4032) || (ir1 == 4095);

    const unsigned ones2 = 0x3C003C00u;
    const unsigned onesB[2] = {ones2, ones2};

    float oacc[4][4] = {};
    float lacc[4] = {};
    int tcur = t0;

    for (int it = 0; it < cnt; it++) {
        const int cur = it & 1;
        const int tcomp = tcur;
        const int j0 = tcomp * 64;

        cp_wait0();
        __syncthreads();
        if (it + 1 < cnt) {
            const int tnext = hasG ? (it + 1) : (tlo + it + 1);
            const int jn = tnext * 64;
            const int nxt = 1 - cur;
            if (doK) cp16(&Ks[nxt][k_row][k_seg], &kb[(size_t)(jn + k_row) * HD + k_seg]);
            else     cp16(&Vt[nxt][v_row][v_seg], &vbt[(size_t)v_row * LDIM + jn + v_seg]);
            cp_commit();
            tcur = tnext;
        }

        // S = Q @ K^T
        float sacc[4][4] = {};
        #pragma unroll
        for (int nb = 0; nb < 4; nb++) {
            int jn = wc * 32 + nb * 8 + g;
            #pragma unroll
            for (int ks = 0; ks < 2; ks++) {
                unsigned bk[2] = {*(const unsigned*)&Ks[cur][jn][16 * ks + 2 * tg],
                                  *(const unsigned*)&Ks[cur][jn][16 * ks + 2 * tg + 8]};
                mma16(sacc[nb], aq[ks], bk);
            }
        }

        // exact full-validity: tile fully in-band iff i0-385 <= 64*tt <= i0+449
        const bool mtile = hasG || (64 * tcomp < i0 - 385) || (64 * tcomp > i0 + 449);
        if (mtile) {
            #pragma unroll
            for (int nb = 0; nb < 4; nb++) {
                int jb = j0 + wc * 32 + nb * 8 + 2 * tg;
                int jb1 = jb + 1;
                bool jg0 = (jb == 0) || (jb == 63) || (jb == 4032) || (jb == 4095);
                bool jg1 = (jb1 == 0) || (jb1 == 63) || (jb1 == 4032) || (jb1 == 4095);
                int d00 = ir0 - jb, d01 = ir0 - jb1, d10 = ir1 - jb, d11 = ir1 - jb1;
                if (!(ig0 || jg0 || (d00 <= 512 && d00 >= -512))) sacc[nb][0] = -1e30f;
                if (!(ig0 || jg1 || (d01 <= 512 && d01 >= -512))) sacc[nb][1] = -1e30f;
                if (!(ig1 || jg0 || (d10 <= 512 && d10 >= -512))) sacc[nb][2] = -1e30f;
                if (!(ig1 || jg1 || (d11 <= 512 && d11 >= -512))) sacc[nb][3] = -1e30f;
            }
        }

        #pragma unroll
        for (int ks = 0; ks < 2; ks++) {
            unsigned ap[4];
            ap[0] = ex2h2(pk2(sacc[2 * ks][0],     sacc[2 * ks][1]));
            ap[1] = ex2h2(pk2(sacc[2 * ks][2],     sacc[2 * ks][3]));
            ap[2] = ex2h2(pk2(sacc[2 * ks + 1][0], sacc[2 * ks + 1][1]));
            ap[3] = ex2h2(pk2(sacc[2 * ks + 1][2], sacc[2 * ks + 1][3]));
            mma16(lacc, ap, onesB);
            const int jcol = wc * 32 + 16 * ks + 2 * tg;
            #pragma unroll
            for (int nb2 = 0; nb2 < 4; nb2++) {
                int cn = nb2 * 8 + g;
                unsigned bv[2] = {*(const unsigned*)&Vt[cur][cn][jcol],
                                  *(const unsigned*)&Vt[cur][cn][jcol + 8]};
                mma16(oacc[nb2], ap, bv);
            }
        }
    }

    // Global-token epilogue (non-hasG; wc==0 warps cover all 128 rows)
    if (!hasG && wc == 0) {
        float sg[4] = {};
        #pragma unroll
        for (int ks = 0; ks < 2; ks++) {
            unsigned bg[2] = {*(const unsigned*)&GsK[g][16 * ks + 2 * tg],
                              *(const unsigned*)&GsK[g][16 * ks + 2 * tg + 8]};
            mma16(sg, aq[ks], bg);
        }
        const bool leadOK  = (tlo > 0);
        const bool trailOK = (thi < 63);
        const int c0i = 2 * tg, c1i = 2 * tg + 1;
        const bool v0 = (c0i < 2) ? leadOK : (c0i < 4 ? trailOK : false);
        const bool v1 = (c1i < 2) ? leadOK : (c1i < 4 ? trailOK : false);
        if (!v0) { sg[0] = -1e30f; sg[2] = -1e30f; }
        if (!v1) { sg[1] = -1e30f; sg[3] = -1e30f; }
        unsigned apg[4] = {ex2h2(pk2(sg[0], sg[1])), ex2h2(pk2(sg[2], sg[3])), 0u, 0u};
        mma16(lacc, apg, onesB);
        #pragma unroll
        for (int nb2 = 0; nb2 < 4; nb2++) {
            int cn = nb2 * 8 + g;
            unsigned bvg[2] = {*(const unsigned*)&Vgt[cn][2 * tg], 0u};
            mma16(oacc[nb2], apg, bvg);
        }
    }

    if (tg == 0) { Lsm[r0][wc] = lacc[0]; Lsm[r1][wc] = lacc[2]; }
    if (wc == 1) {
        #pragma unroll
        for (int nb2 = 0; nb2 < 4; nb2++) {
            int c0 = nb2 * 8 + 2 * tg;
            Red[r0][c0] = oacc[nb2][0]; Red[r0][c0 + 1] = oacc[nb2][1];
            Red[r1][c0] = oacc[nb2][2]; Red[r1][c0 + 1] = oacc[nb2][3];
        }
    }
    __syncthreads();

    if (wc == 0) {
        float inv0 = 1.f / (Lsm[r0][0] + Lsm[r0][1]);
        float inv1 = 1.f / (Lsm[r1][0] + Lsm[r1][1]);
        const int b = bh >> 3, h = bh & 7;
        #pragma unroll
        for (int nb2 = 0; nb2 < 4; nb2++) {
            int c0 = nb2 * 8 + 2 * tg;
            float o0 = (oacc[nb2][0] + Red[r0][c0])     * inv0;
            float o1 = (oacc[nb2][1] + Red[r0][c0 + 1]) * inv0;
            float o2 = (oacc[nb2][2] + Red[r1][c0])     * inv1;
            float o3 = (oacc[nb2][3] + Red[r1][c0 + 1]) * inv1;
            g_o[((size_t)b * LDIM + ir0) * CDIM + c0 * 8 + h]       = __float2half_rn(o0);
            g_o[((size_t)b * LDIM + ir0) * CDIM + (c0 + 1) * 8 + h] = __float2half_rn(o1);
            g_o[((size_t)b * LDIM + ir1) * CDIM + c0 * 8 + h]       = __float2half_rn(o2);
            g_o[((size_t)b * LDIM + ir1) * CDIM + (c0 + 1) * 8 + h] = __float2half_rn(o3);
        }
    }
}

// ---------------------------------------------------------------------------
// Kernel 3: out via fp16 mma; 2-stage cp.async (EXACT R14 config).
// ---------------------------------------------------------------------------
__global__ void __launch_bounds__(256) out_gemm(const float* __restrict__ b2,
                                               float* __restrict__ out) {
    __shared__ __half Wt[2][64][40];
    __shared__ __half Os[2][64][40];

    const int b  = blockIdx.z;
    const int m0 = blockIdx.x * 64;
    const int n0 = blockIdx.y * 64;
    const int t  = threadIdx.x;
    const int lane = t & 31;
    const int warp = t >> 5;
    const int wr = warp >> 1;
    const int wc = warp & 1;
    const int g  = lane >> 2;
    const int tg = lane & 3;

    const __half* ob = g_o + (size_t)b * LDIM * CDIM;
    float acc[4][4] = {};

    const int s_row = t >> 2, s_seg = (t & 3) * 8;

    cp16(&Wt[0][s_row][s_seg], &g_w2t[(size_t)(n0 + s_row) * CDIM + s_seg]);
    cp16(&Os[0][s_row][s_seg], &ob[(size_t)(m0 + s_row) * CDIM + s_seg]);
    cp_commit();

    #pragma unroll
    for (int i = 0; i < 8; i++) {
        const int cur = i & 1;
        cp_wait0();
        __syncthreads();
        if (i < 7) {
            const int nxt = 1 - cur;
            const int kn = (i + 1) * 32;
            cp16(&Wt[nxt][s_row][s_seg], &g_w2t[(size_t)(n0 + s_row) * CDIM + kn + s_seg]);
            cp16(&Os[nxt][s_row][s_seg], &ob[(size_t)(m0 + s_row) * CDIM + kn + s_seg]);
            cp_commit();
        }
        #pragma unroll
        for (int ks = 0; ks < 2; ks++) {
            unsigned af[4];
            af[0] = *(const unsigned*)&Wt[cur][wr * 16 + g][16 * ks + 2 * tg];
            af[1] = *(const unsigned*)&Wt[cur][wr * 16 + g + 8][16 * ks + 2 * tg];
            af[2] = *(const unsigned*)&Wt[cur][wr * 16 + g][16 * ks + 2 * tg + 8];
            af[3] = *(const unsigned*)&Wt[cur][wr * 16 + g + 8][16 * ks + 2 * tg + 8];
            #pragma unroll
            for (int mb = 0; mb < 4; mb++) {
                int mc = wc * 32 + mb * 8 + g;
                unsigned bf[2] = {*(const unsigned*)&Os[cur][mc][16 * ks + 2 * tg],
                                  *(const unsigned*)&Os[cur][mc][16 * ks + 2 * tg + 8]};
                mma16(acc[mb], af, bf);
            }
        }
    }

    const int n_r0 = n0 + wr * 16 + g;
    const int n_r1 = n_r0 + 8;
    const float bias0 = b2[n_r0];
    const float bias1 = b2[n_r1];
    #pragma unroll
    for (int mb = 0; mb < 4; mb++) {
        int mA = m0 + wc * 32 + mb * 8 + 2 * tg;
        float2 v0 = {acc[mb][0] + bias0, acc[mb][1] + bias0};
        float2 v1 = {acc[mb][2] + bias1, acc[mb][3] + bias1};
        *(float2*)&out[((size_t)b * CDIM + n_r0) * LDIM + mA] = v0;
        *(float2*)&out[((size_t)b * CDIM + n_r1) * LDIM + mA] = v1;
    }
}

// ---------------------------------------------------------------------------
extern "C" void kernel_launch(void* const* d_in, const int* in_sizes, int n_in,
                              void* d_out, int out_size) {
    const float* x  = (const float*)d_in[0];
    const float* w1 = (const float*)d_in[1];
    const float* b1 = (const float*)d_in[2];
    const float* w2 = (const float*)d_in[3];
    const float* b2 = (const float*)d_in[4];
    float* out = (float*)d_out;

    __half *xh, *w1t, *w2t;
    cudaGetSymbolAddress((void**)&xh,  g_xh);
    cudaGetSymbolAddress((void**)&w1t, g_w1t);
    cudaGetSymbolAddress((void**)&w2t, g_w2t);

    transpose_f2h<<<dim3(LDIM / 32, CDIM / 32, BSZ), dim3(32, 8)>>>(x, xh, CDIM, LDIM);
    transpose_f2h<<<dim3(N3C / 32, CDIM / 32, 1),  dim3(32, 8)>>>(w1, w1t, CDIM, N3C);
    transpose_f2h<<<dim3(CDIM / 32, CDIM / 32, 1), dim3(32, 8)>>>(w2, w2t, CDIM, CDIM);

    qkv_gemm<<<dim3(LDIM / 64, N3C / 64, BSZ), 256>>>(b1);
    attn_kernel<<<dim3(LDIM / 128, BSZ * HEADS), 512>>>();
    out_gemm<<<dim3(LDIM / 64, CDIM / 64, BSZ), 256>>>(b2, out);
}

// round 17
// speedup vs baseline: 1.1650x; 1.1650x over previous
#include <cuda_runtime.h>
#include <cuda_fp16.h>
#include <math.h>

#define BSZ   2
#define CDIM  256
#define LDIM  4096
#define HEADS 8
#define HD    32
#define N3C   768

// fp16 scratch
__device__ __half g_xh [BSZ*LDIM*CDIM];   // x^T  [b][L][C]
__device__ __half g_w1t[N3C*CDIM];        // w1^T [768][256]
__device__ __half g_w2t[CDIM*CDIM];       // w2^T [256][256]
__device__ __half g_q[BSZ*HEADS*LDIM*HD]; // [bh][L][32]
__device__ __half g_k[BSZ*HEADS*LDIM*HD]; // [bh][L][32]
__device__ __half g_v[BSZ*HEADS*LDIM*HD]; // [bh][c][L] channel-major
__device__ __half g_o[BSZ*LDIM*CDIM];     // [b][L][C]

// fp16 m16n8k16
__device__ __forceinline__ void mma16(float* c, const unsigned* a, const unsigned* b) {
    asm volatile(
        "mma.sync.aligned.m16n8k16.row.col.f32.f16.f16.f32 "
        "{%0,%1,%2,%3},{%4,%5,%6,%7},{%8,%9},{%0,%1,%2,%3};"
        : "+f"(c[0]), "+f"(c[1]), "+f"(c[2]), "+f"(c[3])
        : "r"(a[0]), "r"(a[1]), "r"(a[2]), "r"(a[3]), "r"(b[0]), "r"(b[1]));
}

__device__ __forceinline__ unsigned pk2(float lo, float hi) {
    unsigned r;
    asm("cvt.rn.f16x2.f32 %0, %1, %2;" : "=r"(r) : "f"(hi), "f"(lo));
    return r;
}
__device__ __forceinline__ unsigned ex2h2(unsigned s) {
    unsigned r;
    asm("ex2.approx.f16x2 %0, %1;" : "=r"(r) : "r"(s));
    return r;
}

__device__ __forceinline__ void cp16(void* s, const void* g) {
    unsigned sa = (unsigned)__cvta_generic_to_shared(s);
    asm volatile("cp.async.cg.shared.global [%0], [%1], 16;" :: "r"(sa), "l"(g));
}
__device__ __forceinline__ void cp_commit() { asm volatile("cp.async.commit_group;"); }
__device__ __forceinline__ void cp_wait0()  { asm volatile("cp.async.wait_group 0;"); }

// ldmatrix x4: 4 8x8 fp16 tiles, one address per lane (row of its tile)
__device__ __forceinline__ void ldm4(unsigned* r, const void* p) {
    unsigned a = (unsigned)__cvta_generic_to_shared(p);
    asm volatile("ldmatrix.sync.aligned.m8n8.x4.shared.b16 {%0,%1,%2,%3}, [%4];"
        : "=r"(r[0]), "=r"(r[1]), "=r"(r[2]), "=r"(r[3]) : "r"(a));
}

// ---------------------------------------------------------------------------
// Transpose + f32->f16 convert: dst[c][r] = (half)src[r][c]
// ---------------------------------------------------------------------------
__global__ void transpose_f2h(const float* __restrict__ src, __half* __restrict__ dst,
                              int rows, int cols) {
    __shared__ float tile[32][33];
    const int bz = blockIdx.z;
    src += (size_t)bz * rows * cols;
    dst += (size_t)bz * rows * cols;
    const int c0 = blockIdx.x * 32, r0 = blockIdx.y * 32;
    const int tx = threadIdx.x, ty = threadIdx.y;
    #pragma unroll
    for (int i = 0; i < 4; i++)
        tile[ty + 8 * i][tx] = src[(size_t)(r0 + ty + 8 * i) * cols + c0 + tx];
    __syncthreads();
    #pragma unroll
    for (int i = 0; i < 4; i++)
        dst[(size_t)(c0 + ty + 8 * i) * rows + r0 + tx] = __float2half_rn(tile[tx][ty + 8 * i]);
}

// ---------------------------------------------------------------------------
// Kernel 1: qkv via fp16 mma; 2-stage cp.async; ldmatrix fragment loads.
// ---------------------------------------------------------------------------
__global__ void __launch_bounds__(256) qkv_gemm(const float* __restrict__ b1) {
    __shared__ __half Wt[2][64][40];
    __shared__ __half Xt[2][64][40];

    const int b  = blockIdx.z;
    const int m0 = blockIdx.x * 64;
    const int n0 = blockIdx.y * 64;
    const int t  = threadIdx.x;
    const int lane = t & 31;
    const int warp = t >> 5;
    const int wr = warp >> 1;
    const int wc = warp & 1;
    const int g  = lane >> 2;
    const int tg = lane & 3;

    const __half* xb = g_xh + (size_t)b * LDIM * CDIM;
    float acc[4][4] = {};

    const int s_row = t >> 2, s_seg = (t & 3) * 8;
    // ldmatrix source coords
    const int a_row = lane & 15, a_col = (lane >> 4) * 8;   // A 16x16
    const int b_row = lane & 7,  b_col = (lane >> 3) * 8;   // B 8x32

    cp16(&Wt[0][s_row][s_seg], &g_w1t[(size_t)(n0 + s_row) * CDIM + s_seg]);
    cp16(&Xt[0][s_row][s_seg], &xb[(size_t)(m0 + s_row) * CDIM + s_seg]);
    cp_commit();

    #pragma unroll
    for (int i = 0; i < 8; i++) {
        const int cur = i & 1;
        cp_wait0();
        __syncthreads();
        if (i < 7) {
            const int nxt = 1 - cur;
            const int kn = (i + 1) * 32;
            cp16(&Wt[nxt][s_row][s_seg], &g_w1t[(size_t)(n0 + s_row) * CDIM + kn + s_seg]);
            cp16(&Xt[nxt][s_row][s_seg], &xb[(size_t)(m0 + s_row) * CDIM + kn + s_seg]);
            cp_commit();
        }
        unsigned af[2][4];
        ldm4(af[0], &Wt[cur][wr * 16 + a_row][a_col]);
        ldm4(af[1], &Wt[cur][wr * 16 + a_row][16 + a_col]);
        #pragma unroll
        for (int mb = 0; mb < 4; mb++) {
            unsigned bf[4];
            ldm4(bf, &Xt[cur][wc * 32 + mb * 8 + b_row][b_col]);
            mma16(acc[mb], af[0], bf);
            mma16(acc[mb], af[1], bf + 2);
        }
    }

    const float q_scale = 0.1767766952966368811f * 1.4426950408889634f;
    const int n_r0 = n0 + wr * 16 + g;
    const int n_r1 = n_r0 + 8;
    const int k3_0 = n_r0 % 3, h_0 = (n_r0 / 3) & 7, c_0 = n_r0 / 24;
    const int k3_1 = n_r1 % 3, h_1 = (n_r1 / 3) & 7, c_1 = n_r1 / 24;
    const float bias0 = b1[n_r0], bias1 = b1[n_r1];
    const float sc0 = (k3_0 == 0) ? q_scale : 1.f;
    const float sc1 = (k3_1 == 0) ? q_scale : 1.f;
    const int bh0 = b * HEADS + h_0, bh1 = b * HEADS + h_1;

    #pragma unroll
    for (int mb = 0; mb < 4; mb++) {
        int mA = m0 + wc * 32 + mb * 8 + 2 * tg;
        float v00 = (acc[mb][0] + bias0) * sc0, v01 = (acc[mb][1] + bias0) * sc0;
        float v10 = (acc[mb][2] + bias1) * sc1, v11 = (acc[mb][3] + bias1) * sc1;
        if (k3_0 == 2) {
            *(__half2*)&g_v[((size_t)bh0 * HD + c_0) * LDIM + mA] = __floats2half2_rn(v00, v01);
        } else {
            __half* d = (k3_0 == 0) ? g_q : g_k;
            d[((size_t)bh0 * LDIM + mA)     * HD + c_0] = __float2half_rn(v00);
            d[((size_t)bh0 * LDIM + mA + 1) * HD + c_0] = __float2half_rn(v01);
        }
        if (k3_1 == 2) {
            *(__half2*)&g_v[((size_t)bh1 * HD + c_1) * LDIM + mA] = __floats2half2_rn(v10, v11);
        } else {
            __half* d = (k3_1 == 0) ? g_q : g_k;
            d[((size_t)bh1 * LDIM + mA)     * HD + c_1] = __float2half_rn(v10);
            d[((size_t)bh1 * LDIM + mA + 1) * HD + c_1] = __float2half_rn(v11);
        }
    }
}

// ---------------------------------------------------------------------------
// Kernel 2: banded attention (R14 structure); ldmatrix fragment loads.
// ---------------------------------------------------------------------------
__global__ void __launch_bounds__(256) attn_kernel() {
    __shared__ __half Qs[64][40];
    __shared__ __half Ks[2][64][40];
    __shared__ __half Vt[2][32][72];
    __shared__ __half GsK[8][40];
    __shared__ __half Vgt[32][12];
    __shared__ float  Red[64][33];
    __shared__ float  Lsm[64][2];

    const int qt = blockIdx.x;
    const int bh = blockIdx.y;
    const int i0 = qt * 64;
    const int t  = threadIdx.x;
    const int lane = t & 31;
    const int warp = t >> 5;
    const int wr = warp >> 1;
    const int wc = warp & 1;
    const int g  = lane >> 2;
    const int tg = lane & 3;

    const __half* qb  = g_q + (size_t)bh * LDIM * HD;
    const __half* kb  = g_k + (size_t)bh * LDIM * HD;
    const __half* vbt = g_v + (size_t)bh * HD * LDIM;

    const int k_row = t >> 2, k_seg = t & 3;
    const int v_c   = t >> 3, v_seg = t & 7;
    const int a_row = lane & 15, a_col = (lane >> 4) * 8;
    const int b_row = lane & 7,  b_col = (lane >> 3) * 8;

    const bool hasG = (qt == 0) || (qt == 63);
    const int  tlo  = max(0, i0 - 512) >> 6;
    const int  thi  = min(LDIM - 1, i0 + 63 + 512) >> 6;
    const int  cnt  = hasG ? 64 : (thi - tlo + 1);
    const int  t0   = hasG ? 0 : tlo;

    cp16(&Qs[k_row][k_seg * 8], &qb[(size_t)(i0 + k_row) * HD + k_seg * 8]);

    if (!hasG) {
        if (t < 16) {
            int row = t >> 2, seg = t & 3;
            int jr = (row == 0) ? 0 : (row == 1) ? 63 : (row == 2) ? 4032 : 4095;
            *(uint4*)&GsK[row][seg * 8] = *(const uint4*)&kb[(size_t)jr * HD + seg * 8];
        } else if (t < 32) {
            int row = 4 + ((t - 16) >> 2), seg = t & 3;
            uint4 z = {0u, 0u, 0u, 0u};
            *(uint4*)&GsK[row][seg * 8] = z;
        } else if (t < 64) {
            int c = t - 32;
            Vgt[c][0] = vbt[(size_t)c * LDIM + 0];
            Vgt[c][1] = vbt[(size_t)c * LDIM + 63];
            Vgt[c][2] = vbt[(size_t)c * LDIM + 4032];
            Vgt[c][3] = vbt[(size_t)c * LDIM + 4095];
            #pragma unroll
            for (int jj = 4; jj < 12; jj++) Vgt[c][jj] = __float2half(0.f);
        }
    }
    {
        const int j0 = t0 * 64;
        cp16(&Ks[0][k_row][k_seg * 8], &kb[(size_t)(j0 + k_row) * HD + k_seg * 8]);
        cp16(&Vt[0][v_c][v_seg * 8],   &vbt[(size_t)v_c * LDIM + j0 + v_seg * 8]);
        cp_commit();
    }
    cp_wait0();
    __syncthreads();

    unsigned aq[2][4];
    ldm4(aq[0], &Qs[wr * 16 + a_row][a_col]);
    ldm4(aq[1], &Qs[wr * 16 + a_row][16 + a_col]);

    const int r0 = wr * 16 + g;
    const int r1 = r0 + 8;
    const int ir0 = i0 + r0, ir1 = i0 + r1;
    const bool ig0 = (ir0 == 0) || (ir0 == 63) || (ir0 == 4032) || (ir0 == 4095);
    const bool ig1 = (ir1 == 0) || (ir1 == 63) || (ir1 == 4032) || (ir1 == 4095);

    const unsigned ones2 = 0x3C003C00u;
    const unsigned onesB[2] = {ones2, ones2};

    float oacc[4][4] = {};
    float lacc[4] = {};
    int tcur = t0;

    for (int it = 0; it < cnt; it++) {
        const int cur = it & 1;
        const int tcomp = tcur;
        const int j0 = tcomp * 64;

        cp_wait0();
        __syncthreads();
        if (it + 1 < cnt) {
            const int tnext = hasG ? (it + 1) : (tlo + it + 1);
            const int jn = tnext * 64;
            const int nxt = 1 - cur;
            cp16(&Ks[nxt][k_row][k_seg * 8], &kb[(size_t)(jn + k_row) * HD + k_seg * 8]);
            cp16(&Vt[nxt][v_c][v_seg * 8],   &vbt[(size_t)v_c * LDIM + jn + v_seg * 8]);
            cp_commit();
            tcur = tnext;
        }

        // S = Q @ K^T : per nb one ldmatrix.x4 gives both ks B-frags
        float sacc[4][4] = {};
        #pragma unroll
        for (int nb = 0; nb < 4; nb++) {
            unsigned bk[4];
            ldm4(bk, &Ks[cur][wc * 32 + nb * 8 + b_row][b_col]);
            mma16(sacc[nb], aq[0], bk);
            mma16(sacc[nb], aq[1], bk + 2);
        }

        if (hasG || (tcomp == tlo) || (tcomp == thi)) {
            #pragma unroll
            for (int nb = 0; nb < 4; nb++) {
                int jb = j0 + wc * 32 + nb * 8 + 2 * tg;
                int jb1 = jb + 1;
                bool jg0 = (jb == 0) || (jb == 63) || (jb == 4032) || (jb == 4095);
                bool jg1 = (jb1 == 0) || (jb1 == 63) || (jb1 == 4032) || (jb1 == 4095);
                int d00 = ir0 - jb, d01 = ir0 - jb1, d10 = ir1 - jb, d11 = ir1 - jb1;
                if (!(ig0 || jg0 || (d00 <= 512 && d00 >= -512))) sacc[nb][0] = -1e30f;
                if (!(ig0 || jg1 || (d01 <= 512 && d01 >= -512))) sacc[nb][1] = -1e30f;
                if (!(ig1 || jg0 || (d10 <= 512 && d10 >= -512))) sacc[nb][2] = -1e30f;
                if (!(ig1 || jg1 || (d11 <= 512 && d11 >= -512))) sacc[nb][3] = -1e30f;
            }
        }

        // P = exp2(S); both ks A-frags, lsum mmas, then PV with ldmatrix B
        unsigned ap[2][4];
        #pragma unroll
        for (int ks = 0; ks < 2; ks++) {
            ap[ks][0] = ex2h2(pk2(sacc[2 * ks][0],     sacc[2 * ks][1]));
            ap[ks][1] = ex2h2(pk2(sacc[2 * ks][2],     sacc[2 * ks][3]));
            ap[ks][2] = ex2h2(pk2(sacc[2 * ks + 1][0], sacc[2 * ks + 1][1]));
            ap[ks][3] = ex2h2(pk2(sacc[2 * ks + 1][2], sacc[2 * ks + 1][3]));
            mma16(lacc, ap[ks], onesB);
        }
        #pragma unroll
        for (int nb2 = 0; nb2 < 4; nb2++) {
            unsigned bv[4];
            ldm4(bv, &Vt[cur][nb2 * 8 + b_row][wc * 32 + b_col]);
            mma16(oacc[nb2], ap[0], bv);
            mma16(oacc[nb2], ap[1], bv + 2);
        }
    }

    if (!hasG && wc == 0) {
        float sg[4] = {};
        #pragma unroll
        for (int ks = 0; ks < 2; ks++) {
            unsigned bg[2] = {*(const unsigned*)&GsK[g][16 * ks + 2 * tg],
                              *(const unsigned*)&GsK[g][16 * ks + 2 * tg + 8]};
            mma16(sg, aq[ks], bg);
        }
        const bool leadOK  = (tlo > 0);
        const bool trailOK = (thi < 63);
        const int c0i = 2 * tg, c1i = 2 * tg + 1;
        const bool v0 = (c0i < 2) ? leadOK : (c0i < 4 ? trailOK : false);
        const bool v1 = (c1i < 2) ? leadOK : (c1i < 4 ? trailOK : false);
        if (!v0) { sg[0] = -1e30f; sg[2] = -1e30f; }
        if (!v1) { sg[1] = -1e30f; sg[3] = -1e30f; }
        unsigned apg[4] = {ex2h2(pk2(sg[0], sg[1])), ex2h2(pk2(sg[2], sg[3])), 0u, 0u};
        mma16(lacc, apg, onesB);
        #pragma unroll
        for (int nb2 = 0; nb2 < 4; nb2++) {
            int cn = nb2 * 8 + g;
            unsigned bvg[2] = {*(const unsigned*)&Vgt[cn][2 * tg], 0u};
            mma16(oacc[nb2], apg, bvg);
        }
    }

    if (tg == 0) { Lsm[r0][wc] = lacc[0]; Lsm[r1][wc] = lacc[2]; }
    if (wc == 1) {
        #pragma unroll
        for (int nb2 = 0; nb2 < 4; nb2++) {
            int c0 = nb2 * 8 + 2 * tg;
            Red[r0][c0] = oacc[nb2][0]; Red[r0][c0 + 1] = oacc[nb2][1];
            Red[r1][c0] = oacc[nb2][2]; Red[r1][c0 + 1] = oacc[nb2][3];
        }
    }
    __syncthreads();

    if (wc == 0) {
        float inv0 = 1.f / (Lsm[r0][0] + Lsm[r0][1]);
        float inv1 = 1.f / (Lsm[r1][0] + Lsm[r1][1]);
        const int b = bh >> 3, h = bh & 7;
        #pragma unroll
        for (int nb2 = 0; nb2 < 4; nb2++) {
            int c0 = nb2 * 8 + 2 * tg;
            float o0 = (oacc[nb2][0] + Red[r0][c0])     * inv0;
            float o1 = (oacc[nb2][1] + Red[r0][c0 + 1]) * inv0;
            float o2 = (oacc[nb2][2] + Red[r1][c0])     * inv1;
            float o3 = (oacc[nb2][3] + Red[r1][c0 + 1]) * inv1;
            g_o[((size_t)b * LDIM + ir0) * CDIM + c0 * 8 + h]       = __float2half_rn(o0);
            g_o[((size_t)b * LDIM + ir0) * CDIM + (c0 + 1) * 8 + h] = __float2half_rn(o1);
            g_o[((size_t)b * LDIM + ir1) * CDIM + c0 * 8 + h]       = __float2half_rn(o2);
            g_o[((size_t)b * LDIM + ir1) * CDIM + (c0 + 1) * 8 + h] = __float2half_rn(o3);
        }
    }
}

// ---------------------------------------------------------------------------
// Kernel 3: out via fp16 mma; 2-stage cp.async; ldmatrix fragment loads.
// ---------------------------------------------------------------------------
__global__ void __launch_bounds__(256) out_gemm(const float* __restrict__ b2,
                                               float* __restrict__ out) {
    __shared__ __half Wt[2][64][40];
    __shared__ __half Os[2][64][40];

    const int b  = blockIdx.z;
    const int m0 = blockIdx.x * 64;
    const int n0 = blockIdx.y * 64;
    const int t  = threadIdx.x;
    const int lane = t & 31;
    const int warp = t >> 5;
    const int wr = warp >> 1;
    const int wc = warp & 1;
    const int g  = lane >> 2;
    const int tg = lane & 3;

    const __half* ob = g_o + (size_t)b * LDIM * CDIM;
    float acc[4][4] = {};

    const int s_row = t >> 2, s_seg = (t & 3) * 8;
    const int a_row = lane & 15, a_col = (lane >> 4) * 8;
    const int b_row = lane & 7,  b_col = (lane >> 3) * 8;

    cp16(&Wt[0][s_row][s_seg], &g_w2t[(size_t)(n0 + s_row) * CDIM + s_seg]);
    cp16(&Os[0][s_row][s_seg], &ob[(size_t)(m0 + s_row) * CDIM + s_seg]);
    cp_commit();

    #pragma unroll
    for (int i = 0; i < 8; i++) {
        const int cur = i & 1;
        cp_wait0();
        __syncthreads();
        if (i < 7) {
            const int nxt = 1 - cur;
            const int kn = (i + 1) * 32;
            cp16(&Wt[nxt][s_row][s_seg], &g_w2t[(size_t)(n0 + s_row) * CDIM + kn + s_seg]);
            cp16(&Os[nxt][s_row][s_seg], &ob[(size_t)(m0 + s_row) * CDIM + kn + s_seg]);
            cp_commit();
        }
        unsigned af[2][4];
        ldm4(af[0], &Wt[cur][wr * 16 + a_row][a_col]);
        ldm4(af[1], &Wt[cur][wr * 16 + a_row][16 + a_col]);
        #pragma unroll
        for (int mb = 0; mb < 4; mb++) {
            unsigned bf[4];
            ldm4(bf, &Os[cur][wc * 32 + mb * 8 + b_row][b_col]);
            mma16(acc[mb], af[0], bf);
            mma16(acc[mb], af[1], bf + 2);
        }
    }

    const int n_r0 = n0 + wr * 16 + g;
    const int n_r1 = n_r0 + 8;
    const float bias0 = b2[n_r0];
    const float bias1 = b2[n_r1];
    #pragma unroll
    for (int mb = 0; mb < 4; mb++) {
        int mA = m0 + wc * 32 + mb * 8 + 2 * tg;
        float2 v0 = {acc[mb][0] + bias0, acc[mb][1] + bias0};
        float2 v1 = {acc[mb][2] + bias1, acc[mb][3] + bias1};
        *(float2*)&out[((size_t)b * CDIM + n_r0) * LDIM + mA] = v0;
        *(float2*)&out[((size_t)b * CDIM + n_r1) * LDIM + mA] = v1;
    }
}

// ---------------------------------------------------------------------------
extern "C" void kernel_launch(void* const* d_in, const int* in_sizes, int n_in,
                              void* d_out, int out_size) {
    const float* x  = (const float*)d_in[0];
    const float* w1 = (const float*)d_in[1];
    const float* b1 = (const float*)d_in[2];
    const float* w2 = (const float*)d_in[3];
    const float* b2 = (const float*)d_in[4];
    float* out = (float*)d_out;

    __half *xh, *w1t, *w2t;
    cudaGetSymbolAddress((void**)&xh,  g_xh);
    cudaGetSymbolAddress((void**)&w1t, g_w1t);
    cudaGetSymbolAddress((void**)&w2t, g_w2t);

    transpose_f2h<<<dim3(LDIM / 32, CDIM / 32, BSZ), dim3(32, 8)>>>(x, xh, CDIM, LDIM);
    transpose_f2h<<<dim3(N3C / 32, CDIM / 32, 1),  dim3(32, 8)>>>(w1, w1t, CDIM, N3C);
    transpose_f2h<<<dim3(CDIM / 32, CDIM / 32, 1), dim3(32, 8)>>>(w2, w2t, CDIM, CDIM);

    qkv_gemm<<<dim3(LDIM / 64, N3C / 64, BSZ), 256>>>(b1);
    attn_kernel<<<dim3(LDIM / 64, BSZ * HEADS), 256>>>();
    out_gemm<<<dim3(LDIM / 64, CDIM / 64, BSZ), 256>>>(b2, out);
}